// round 2
// baseline (speedup 1.0000x reference)
#include <cuda_runtime.h>
#include <math.h>

// Problem constants
#define NB   8192          // batch
#define NV   778           // vertices
#define F    146           // features: 1 + 10 beta + 135 pose_feature
#define KP   160           // padded K for GEMM
#define NO   1008          // 16 joints * 21 out-joints * 3
#define NP   1024          // padded N for GEMM

// ---------------- scratch (device globals; zero-initialized at load) ----------------
__device__ float g_C[KP * NP];     // [f][o], rows >=146 and cols >=1008 stay zero
__device__ float g_X[NB * KP];     // [b][f] features (cols 146..159 written zero)
__device__ float g_A[NB * 192];    // [b][j][3x4] row-major (rot | trans)
__device__ float g_M[NB * NP];     // GEMM output
__device__ float g_Js[480];        // [s][j][c]  s<10, j<16, c<3
__device__ float g_J0[48];         // [j][c]
__device__ float g_W[336];         // [k][j]  k<21, j<16

// =====================================================================
// Kernel 1: C[f, (j,k,d)] = sum_v basis_f[v,d] * w[v,j] * Jr[v,k]
// grid = 146 blocks (one per f), 384 threads; thread t<336 owns (j,k), all 3 d.
// =====================================================================
__global__ __launch_bounds__(384) void precomp_C(
    const float* __restrict__ vt, const float* __restrict__ sd,
    const float* __restrict__ pd, const float* __restrict__ Jr,
    const float* __restrict__ wts)
{
    int f = blockIdx.x;
    const float* brow = (f == 0) ? vt : ((f <= 10) ? (sd + (f - 1) * 2334)
                                                   : (pd + (f - 11) * 2334));
    __shared__ float sB[64 * 3];
    __shared__ float sW[64 * 16];
    __shared__ float sJr[64 * 21];

    int t = threadIdx.x;
    int j = t / 21, k = t % 21;
    bool active = (t < 336);
    float acc0 = 0.f, acc1 = 0.f, acc2 = 0.f;

    for (int v0 = 0; v0 < NV; v0 += 64) {
        int nv = min(64, NV - v0);
        for (int i = t; i < nv * 3;  i += 384) sB[i]  = brow[v0 * 3 + i];
        for (int i = t; i < nv * 16; i += 384) sW[i]  = wts[v0 * 16 + i];
        for (int i = t; i < nv * 21; i += 384) sJr[i] = Jr[v0 * 21 + i];
        __syncthreads();
        if (active) {
            #pragma unroll 2
            for (int v = 0; v < nv; v++) {
                float p = sW[v * 16 + j] * sJr[v * 21 + k];
                acc0 = fmaf(p, sB[v * 3 + 0], acc0);
                acc1 = fmaf(p, sB[v * 3 + 1], acc1);
                acc2 = fmaf(p, sB[v * 3 + 2], acc2);
            }
        }
        __syncthreads();
    }
    if (active) {
        int o = (j * 21 + k) * 3;
        g_C[f * NP + o + 0] = acc0;
        g_C[f * NP + o + 1] = acc1;
        g_C[f * NP + o + 2] = acc2;
    }
}

// =====================================================================
// Kernel 2: small batch-independent reductions: Js, J0, W. One warp per output.
// grid = 108 blocks * 256 threads = 864 warps = 480 + 48 + 336 outputs.
// =====================================================================
__global__ __launch_bounds__(256) void precomp_small(
    const float* __restrict__ vt, const float* __restrict__ sd,
    const float* __restrict__ Jr, const float* __restrict__ wts)
{
    int gw   = blockIdx.x * 8 + (threadIdx.x >> 5);
    int lane = threadIdx.x & 31;
    float acc = 0.f;

    if (gw < 480) {                 // Js[s][j][c]
        int s = gw / 48, r = gw % 48, j = r / 3, c = r % 3;
        for (int v = lane; v < NV; v += 32)
            acc = fmaf(Jr[v * 21 + j], sd[s * 2334 + v * 3 + c], acc);
    } else if (gw < 528) {          // J0[j][c]
        int idx = gw - 480, j = idx / 3, c = idx % 3;
        for (int v = lane; v < NV; v += 32)
            acc = fmaf(Jr[v * 21 + j], vt[v * 3 + c], acc);
    } else {                        // W[k][j]
        int idx = gw - 528, k = idx / 16, j = idx % 16;
        for (int v = lane; v < NV; v += 32)
            acc = fmaf(Jr[v * 21 + k], wts[v * 16 + j], acc);
    }
    #pragma unroll
    for (int off = 16; off > 0; off >>= 1)
        acc += __shfl_down_sync(0xffffffffu, acc, off);
    if (lane == 0) {
        if (gw < 480)      g_Js[gw] = acc;
        else if (gw < 528) g_J0[gw - 480] = acc;
        else               g_W[gw - 528] = acc;
    }
}

// =====================================================================
// Kernel 3: per-batch forward kinematics. One warp per batch.
// Produces g_X[b][160] and g_A[b][16][12].
// =====================================================================
__global__ __launch_bounds__(256) void fk_kernel(
    const float* __restrict__ beta, const float* __restrict__ theta,
    const float* __restrict__ wrist, const float* __restrict__ hc,
    const float* __restrict__ hm)
{
    __shared__ float sE[8][48];        // euler_pose (45)
    __shared__ float sR[8][16][9];     // rotations
    __shared__ float sJ[8][16][3];     // joint positions
    __shared__ float sG[8][16][12];    // global transforms (3x4)

    int w = threadIdx.x >> 5, lane = threadIdx.x & 31;
    int b = blockIdx.x * 8 + w;

    // euler_pose = theta @ hands_comp + hands_mean  (45 values, strip-mined over 32 lanes)
    for (int e = lane; e < 45; e += 32) {
        float v = hm[e];
        #pragma unroll
        for (int s = 0; s < 10; s++)
            v = fmaf(theta[b * 10 + s], hc[s * 45 + e], v);
        sE[w][e] = v;
    }
    __syncwarp();

    // rodrigues for 16 rotations (lane 0 = wrist, lanes 1..15 = hand joints)
    if (lane < 16) {
        float r0, r1, r2;
        if (lane == 0) { r0 = wrist[b * 3]; r1 = wrist[b * 3 + 1]; r2 = wrist[b * 3 + 2]; }
        else { int e = (lane - 1) * 3; r0 = sE[w][e]; r1 = sE[w][e + 1]; r2 = sE[w][e + 2]; }
        float t0 = r0 + 1e-8f, t1 = r1 + 1e-8f, t2 = r2 + 1e-8f;
        float ang = sqrtf(t0 * t0 + t1 * t1 + t2 * t2);
        float inv = 1.0f / ang;
        float x = r0 * inv, y = r1 * inv, z = r2 * inv;
        float s, c;
        sincosf(ang, &s, &c);
        float ic = 1.0f - c;
        float R[9];
        R[0] = 1.0f - ic * (y * y + z * z);
        R[1] = -s * z + ic * x * y;
        R[2] =  s * y + ic * x * z;
        R[3] =  s * z + ic * x * y;
        R[4] = 1.0f - ic * (x * x + z * z);
        R[5] = -s * x + ic * y * z;
        R[6] = -s * y + ic * x * z;
        R[7] =  s * x + ic * y * z;
        R[8] = 1.0f - ic * (x * x + y * y);
        #pragma unroll
        for (int m = 0; m < 9; m++) sR[w][lane][m] = R[m];
        if (lane >= 1) {                      // pose_feature -> X[11..145]
            int base = b * KP + 11 + (lane - 1) * 9;
            #pragma unroll
            for (int m = 0; m < 9; m++)
                g_X[base + m] = R[m] - ((m == 0 || m == 4 || m == 8) ? 1.0f : 0.0f);
        }
    }
    // X header + pads
    if (lane == 0)  g_X[b * KP] = 1.0f;
    if (lane < 10)  g_X[b * KP + 1 + lane] = beta[b * 10 + lane];
    if (lane < 14)  g_X[b * KP + 146 + lane] = 0.0f;

    // joint positions: J[j] = J0[j] + beta @ Js[:,j]
    if (lane < 16) {
        float jx = g_J0[lane * 3 + 0], jy = g_J0[lane * 3 + 1], jz = g_J0[lane * 3 + 2];
        #pragma unroll
        for (int s = 0; s < 10; s++) {
            float bs = beta[b * 10 + s];
            jx = fmaf(bs, g_Js[s * 48 + lane * 3 + 0], jx);
            jy = fmaf(bs, g_Js[s * 48 + lane * 3 + 1], jy);
            jz = fmaf(bs, g_Js[s * 48 + lane * 3 + 2], jz);
        }
        sJ[w][lane][0] = jx; sJ[w][lane][1] = jy; sJ[w][lane][2] = jz;
    }
    __syncwarp();

    // root transform
    if (lane == 0) {
        #pragma unroll
        for (int c = 0; c < 3; c++) {
            #pragma unroll
            for (int d = 0; d < 3; d++) sG[w][0][c * 4 + d] = sR[w][0][c * 3 + d];
            sG[w][0][c * 4 + 3] = sJ[w][0][c];
        }
    }
    __syncwarp();

    // 5 chains of 3 joints each (lanes 0..4)
    if (lane < 5) {
        float pr[9], pt[3];
        #pragma unroll
        for (int c = 0; c < 3; c++) {
            #pragma unroll
            for (int d = 0; d < 3; d++) pr[c * 3 + d] = sG[w][0][c * 4 + d];
            pt[c] = sG[w][0][c * 4 + 3];
        }
        int p = 0;
        #pragma unroll
        for (int st = 0; st < 3; st++) {
            int j = 1 + lane * 3 + st;
            float rj[9];
            #pragma unroll
            for (int m = 0; m < 9; m++) rj[m] = sR[w][j][m];
            float nr[9], nt[3];
            #pragma unroll
            for (int c = 0; c < 3; c++)
                #pragma unroll
                for (int d = 0; d < 3; d++)
                    nr[c * 3 + d] = pr[c * 3 + 0] * rj[0 * 3 + d]
                                  + pr[c * 3 + 1] * rj[1 * 3 + d]
                                  + pr[c * 3 + 2] * rj[2 * 3 + d];
            float dx = sJ[w][j][0] - sJ[w][p][0];
            float dy = sJ[w][j][1] - sJ[w][p][1];
            float dz = sJ[w][j][2] - sJ[w][p][2];
            #pragma unroll
            for (int c = 0; c < 3; c++)
                nt[c] = pr[c * 3 + 0] * dx + pr[c * 3 + 1] * dy + pr[c * 3 + 2] * dz + pt[c];
            #pragma unroll
            for (int c = 0; c < 3; c++) {
                #pragma unroll
                for (int d = 0; d < 3; d++) sG[w][j][c * 4 + d] = nr[c * 3 + d];
                sG[w][j][c * 4 + 3] = nt[c];
            }
            #pragma unroll
            for (int m = 0; m < 9; m++) pr[m] = nr[m];
            pt[0] = nt[0]; pt[1] = nt[1]; pt[2] = nt[2];
            p = j;
        }
    }
    __syncwarp();

    // A[j] = [G_rot | G_trans - G_rot @ J[j]]
    if (lane < 16) {
        float jx = sJ[w][lane][0], jy = sJ[w][lane][1], jz = sJ[w][lane][2];
        #pragma unroll
        for (int c = 0; c < 3; c++) {
            float a0 = sG[w][lane][c * 4 + 0];
            float a1 = sG[w][lane][c * 4 + 1];
            float a2 = sG[w][lane][c * 4 + 2];
            float at = sG[w][lane][c * 4 + 3] - (a0 * jx + a1 * jy + a2 * jz);
            int base = b * 192 + lane * 12 + c * 4;
            g_A[base + 0] = a0; g_A[base + 1] = a1;
            g_A[base + 2] = a2; g_A[base + 3] = at;
        }
    }
}

// =====================================================================
// Kernel 4: GEMM  M[8192,1024] = X[8192,160] * C[160,1024]
// 128x128 tiles, BK=16, 8x8 microtiles, packed fma.rn.f32x2 (FFMA2).
// =====================================================================
#define BM 128
#define BN 128
#define BK 16
__global__ __launch_bounds__(256) void gemm_kernel()
{
    __shared__ float Xs[BK][BM + 4];
    __shared__ float Cs[BK][BN];

    int tid = threadIdx.x;
    int tx = tid & 15;          // bn micro index
    int ty = tid >> 4;          // bm micro index
    int bm0 = blockIdx.y * BM;
    int bn0 = blockIdx.x * BN;

    unsigned long long acc[8][4];
    #pragma unroll
    for (int i = 0; i < 8; i++)
        #pragma unroll
        for (int p = 0; p < 4; p++) acc[i][p] = 0ull;

    for (int k0 = 0; k0 < KP; k0 += BK) {
        // load X tile (transpose into Xs[k][bm])
        #pragma unroll
        for (int r = 0; r < 2; r++) {
            int id = tid + 256 * r;
            int bm = id >> 2, k4 = (id & 3) * 4;
            float4 v = *(const float4*)&g_X[(bm0 + bm) * KP + k0 + k4];
            Xs[k4 + 0][bm] = v.x; Xs[k4 + 1][bm] = v.y;
            Xs[k4 + 2][bm] = v.z; Xs[k4 + 3][bm] = v.w;
        }
        // load C tile (direct)
        #pragma unroll
        for (int r = 0; r < 2; r++) {
            int id = tid + 256 * r;
            int kr = id >> 5, c4 = (id & 31) * 4;
            *(float4*)&Cs[kr][c4] = *(const float4*)&g_C[(k0 + kr) * NP + bn0 + c4];
        }
        __syncthreads();

        #pragma unroll
        for (int k = 0; k < BK; k++) {
            float4 a0 = *(const float4*)&Xs[k][ty * 8];
            float4 a1 = *(const float4*)&Xs[k][ty * 8 + 4];
            ulonglong2 b0 = *(const ulonglong2*)&Cs[k][tx * 8];
            ulonglong2 b1 = *(const ulonglong2*)&Cs[k][tx * 8 + 4];
            float av[8] = {a0.x, a0.y, a0.z, a0.w, a1.x, a1.y, a1.z, a1.w};
            unsigned long long bp[4] = {b0.x, b0.y, b1.x, b1.y};
            #pragma unroll
            for (int i = 0; i < 8; i++) {
                unsigned long long ap;
                asm("mov.b64 %0, {%1, %1};" : "=l"(ap) : "f"(av[i]));
                #pragma unroll
                for (int p = 0; p < 4; p++)
                    asm("fma.rn.f32x2 %0, %1, %2, %0;"
                        : "+l"(acc[i][p]) : "l"(ap), "l"(bp[p]));
            }
        }
        __syncthreads();
    }

    #pragma unroll
    for (int i = 0; i < 8; i++) {
        int bm = bm0 + ty * 8 + i;
        ulonglong2 s0, s1;
        s0.x = acc[i][0]; s0.y = acc[i][1];
        s1.x = acc[i][2]; s1.y = acc[i][3];
        *(ulonglong2*)&g_M[bm * NP + bn0 + tx * 8]     = s0;
        *(ulonglong2*)&g_M[bm * NP + bn0 + tx * 8 + 4] = s1;
    }
}

// =====================================================================
// Kernel 5: joints[b,k,c] = sum_j ( A[b,j,c,:3].M[b,j,k,:] + A[b,j,c,3]*W[k,j] )
// One warp per batch, M staged through shared memory.
// =====================================================================
__global__ __launch_bounds__(256) void reduce_kernel(float* __restrict__ out)
{
    __shared__ float Msh[8][1008];
    __shared__ float Ash[8][192];
    __shared__ float Wsh[336];

    int w = threadIdx.x >> 5, lane = threadIdx.x & 31;
    int b = blockIdx.x * 8 + w;

    for (int i = threadIdx.x; i < 336; i += 256) Wsh[i] = g_W[i];
    #pragma unroll
    for (int r = 0; r < 8; r++) {
        int idx = lane + r * 32;
        if (idx < 252)
            *(float4*)&Msh[w][idx * 4] = *(const float4*)&g_M[b * NP + idx * 4];
    }
    #pragma unroll
    for (int r = 0; r < 2; r++) {
        int idx = lane + r * 32;
        if (idx < 48)
            *(float4*)&Ash[w][idx * 4] = *(const float4*)&g_A[b * 192 + idx * 4];
    }
    __syncthreads();

    #pragma unroll
    for (int rep = 0; rep < 2; rep++) {
        int o = lane + rep * 32;
        if (o < 63) {
            int k = o / 3, c = o % 3;
            float acc = 0.f;
            #pragma unroll
            for (int j = 0; j < 16; j++) {
                const float* a = &Ash[w][j * 12 + c * 4];
                const float* m = &Msh[w][(j * 21 + k) * 3];
                acc = fmaf(a[0], m[0], acc);
                acc = fmaf(a[1], m[1], acc);
                acc = fmaf(a[2], m[2], acc);
                acc = fmaf(a[3], Wsh[k * 16 + j], acc);
            }
            out[b * 63 + o] = acc;
        }
    }
}

// =====================================================================
extern "C" void kernel_launch(void* const* d_in, const int* in_sizes, int n_in,
                              void* d_out, int out_size)
{
    const float* beta  = (const float*)d_in[0];
    const float* theta = (const float*)d_in[1];
    const float* wrist = (const float*)d_in[2];
    const float* vt    = (const float*)d_in[3];
    const float* sd    = (const float*)d_in[4];
    const float* pd    = (const float*)d_in[5];
    const float* Jr    = (const float*)d_in[6];
    const float* hc    = (const float*)d_in[7];
    const float* hm    = (const float*)d_in[8];
    const float* wts   = (const float*)d_in[9];
    float* out = (float*)d_out;

    precomp_C<<<146, 384>>>(vt, sd, pd, Jr, wts);
    precomp_small<<<108, 256>>>(vt, sd, Jr, wts);
    fk_kernel<<<1024, 256>>>(beta, theta, wrist, hc, hm);
    gemm_kernel<<<dim3(NP / BN, NB / BM), 256>>>();
    reduce_kernel<<<1024, 256>>>(out);
}

// round 4
// speedup vs baseline: 1.2856x; 1.2856x over previous
#include <cuda_runtime.h>
#include <cuda_fp16.h>
#include <math.h>
#include <stdint.h>

// Problem constants
#define NB   8192          // batch
#define NV   778           // vertices
#define KC   512           // padded K (3x160 split: [Xhi|Xlo|Xhi] vs [Chi|Chi|Clo])
#define NP   1024          // padded N
#define BKC  32            // k per pipeline chunk
#define NCH  16            // 512 / 32

// ---------------- scratch (device globals; zero-initialized at load) ----------------
__device__ __half g_Xh[(size_t)NB * KC];   // [b][k]  A operand fp16 (pads stay zero)
__device__ __half g_Cb[(size_t)KC * NP];   // [k][o]  B operand fp16 (pad rows stay zero)
__device__ float  g_A[NB * 192];           // [b][j][3x4]
__device__ float  g_M[(size_t)NB * NP];    // GEMM output fp32
__device__ float  g_Js[480];
__device__ float  g_J0[48];
__device__ float  g_W[336];

// ---------------- helpers ----------------
__device__ __forceinline__ void write_hl(__half* base, int s, float v) {
    __half h = __float2half(v);
    __half l = __float2half(v - __half2float(h));
    base[s] = h; base[160 + s] = l; base[320 + s] = h;
}
__device__ __forceinline__ void ldsm_x4(uint32_t* r, uint32_t addr) {
    asm volatile("ldmatrix.sync.aligned.m8n8.x4.shared.b16 {%0,%1,%2,%3}, [%4];"
                 : "=r"(r[0]), "=r"(r[1]), "=r"(r[2]), "=r"(r[3]) : "r"(addr));
}
__device__ __forceinline__ void ldsm_x2_t(uint32_t* r, uint32_t addr) {
    asm volatile("ldmatrix.sync.aligned.m8n8.x2.trans.shared.b16 {%0,%1}, [%2];"
                 : "=r"(r[0]), "=r"(r[1]) : "r"(addr));
}
__device__ __forceinline__ void mma16816(float* d, const uint32_t* a, const uint32_t* b) {
    asm volatile("mma.sync.aligned.m16n8k16.row.col.f32.f16.f16.f32 "
                 "{%0,%1,%2,%3}, {%4,%5,%6,%7}, {%8,%9}, {%0,%1,%2,%3};"
                 : "+f"(d[0]), "+f"(d[1]), "+f"(d[2]), "+f"(d[3])
                 : "r"(a[0]), "r"(a[1]), "r"(a[2]), "r"(a[3]), "r"(b[0]), "r"(b[1]));
}
__device__ __forceinline__ void cp16(uint32_t saddr, const void* g) {
    asm volatile("cp.async.cg.shared.global [%0], [%1], 16;" :: "r"(saddr), "l"(g) : "memory");
}
#define CP_COMMIT() asm volatile("cp.async.commit_group;" ::: "memory")
#define CP_WAIT1()  asm volatile("cp.async.wait_group 1;" ::: "memory")
// A staging: 64B rows (32 halfs), swizzle bits[5:4] ^= bits[7:6]
#define SWA(o) ((o) ^ (((o) >> 2) & 0x30))
// B staging: 256B rows (128 halfs), swizzle bits[6:4] ^= bits[10:8]
#define SWB(o) ((o) ^ (((o) >> 4) & 0x70))

// =====================================================================
// Kernel 1: precomp_all — blocks 0..145: C factor (hi/lo fp16, [k][o] layout);
//           blocks 146..172: small reductions (Js, J0, W).
// =====================================================================
__global__ __launch_bounds__(1024) void precomp_all(
    const float* __restrict__ vt, const float* __restrict__ sd,
    const float* __restrict__ pd, const float* __restrict__ Jr,
    const float* __restrict__ wts)
{
    __shared__ float sB[64 * 3];
    __shared__ float sW[64 * 16];
    __shared__ float sJr[64 * 21];
    __shared__ float part[2][1008];

    int t = threadIdx.x;
    int bid = blockIdx.x;

    if (bid < 146) {
        int f = bid;
        const float* brow = (f == 0) ? vt : ((f <= 10) ? (sd + (f - 1) * 2334)
                                                       : (pd + (f - 11) * 2334));
        int vg = t / 336;        // 0..2 (t < 1008)
        int o  = t % 336;
        int j = o / 21, k = o % 21;
        bool act = (t < 1008);
        float a0 = 0.f, a1 = 0.f, a2 = 0.f;

        for (int v0 = 0; v0 < NV; v0 += 64) {
            int nv = min(64, NV - v0);
            for (int i = t; i < nv * 3;  i += 1024) sB[i]  = brow[v0 * 3 + i];
            for (int i = t; i < nv * 16; i += 1024) sW[i]  = wts[v0 * 16 + i];
            for (int i = t; i < nv * 21; i += 1024) sJr[i] = Jr[v0 * 21 + i];
            __syncthreads();
            if (act) {
                for (int v = vg; v < nv; v += 3) {
                    float p = sW[v * 16 + j] * sJr[v * 21 + k];
                    a0 = fmaf(p, sB[v * 3 + 0], a0);
                    a1 = fmaf(p, sB[v * 3 + 1], a1);
                    a2 = fmaf(p, sB[v * 3 + 2], a2);
                }
            }
            __syncthreads();
        }
        if (act && vg > 0) {
            part[vg - 1][o * 3 + 0] = a0;
            part[vg - 1][o * 3 + 1] = a1;
            part[vg - 1][o * 3 + 2] = a2;
        }
        __syncthreads();
        if (t < 336) {
            float v[3];
            v[0] = a0 + part[0][t * 3 + 0] + part[1][t * 3 + 0];
            v[1] = a1 + part[0][t * 3 + 1] + part[1][t * 3 + 1];
            v[2] = a2 + part[0][t * 3 + 2] + part[1][t * 3 + 2];
            #pragma unroll
            for (int c = 0; c < 3; c++) {
                __half ch = __float2half(v[c]);
                __half cl = __float2half(v[c] - __half2float(ch));
                int ol = t * 3 + c;       // (j*21+k)*3+c
                g_Cb[(size_t)f * NP + ol]         = ch;
                g_Cb[(size_t)(160 + f) * NP + ol] = ch;
                g_Cb[(size_t)(320 + f) * NP + ol] = cl;
            }
        }
    } else {
        int gw   = (bid - 146) * 32 + (t >> 5);    // 0..863
        int lane = t & 31;
        float acc = 0.f;
        if (gw < 480) {                 // Js[s][j][c]
            int s = gw / 48, r = gw % 48, j = r / 3, c = r % 3;
            for (int v = lane; v < NV; v += 32)
                acc = fmaf(Jr[v * 21 + j], sd[s * 2334 + v * 3 + c], acc);
        } else if (gw < 528) {          // J0[j][c]
            int idx = gw - 480, j = idx / 3, c = idx % 3;
            for (int v = lane; v < NV; v += 32)
                acc = fmaf(Jr[v * 21 + j], vt[v * 3 + c], acc);
        } else {                        // W[k][j]
            int idx = gw - 528, k = idx / 16, j = idx % 16;
            for (int v = lane; v < NV; v += 32)
                acc = fmaf(Jr[v * 21 + k], wts[v * 16 + j], acc);
        }
        #pragma unroll
        for (int off = 16; off > 0; off >>= 1)
            acc += __shfl_down_sync(0xffffffffu, acc, off);
        if (lane == 0) {
            if (gw < 480)      g_Js[gw] = acc;
            else if (gw < 528) g_J0[gw - 480] = acc;
            else               g_W[gw - 528] = acc;
        }
    }
}

// =====================================================================
// Kernel 2: per-batch forward kinematics. One warp per batch.
// Produces g_Xh[b][512] (hi/lo fp16) and g_A[b][16][12].
// =====================================================================
__global__ __launch_bounds__(256) void fk_kernel(
    const float* __restrict__ beta, const float* __restrict__ theta,
    const float* __restrict__ wrist, const float* __restrict__ hc,
    const float* __restrict__ hm)
{
    __shared__ float sE[8][48];
    __shared__ float sR[8][16][9];
    __shared__ float sJ[8][16][3];
    __shared__ float sG[8][16][12];

    int w = threadIdx.x >> 5, lane = threadIdx.x & 31;
    int b = blockIdx.x * 8 + w;
    __half* xrow = g_Xh + (size_t)b * KC;

    for (int e = lane; e < 45; e += 32) {
        float v = hm[e];
        #pragma unroll
        for (int s = 0; s < 10; s++)
            v = fmaf(theta[b * 10 + s], hc[s * 45 + e], v);
        sE[w][e] = v;
    }
    __syncwarp();

    if (lane < 16) {
        float r0, r1, r2;
        if (lane == 0) { r0 = wrist[b * 3]; r1 = wrist[b * 3 + 1]; r2 = wrist[b * 3 + 2]; }
        else { int e = (lane - 1) * 3; r0 = sE[w][e]; r1 = sE[w][e + 1]; r2 = sE[w][e + 2]; }
        float t0 = r0 + 1e-8f, t1 = r1 + 1e-8f, t2 = r2 + 1e-8f;
        float ang = sqrtf(t0 * t0 + t1 * t1 + t2 * t2);
        float inv = 1.0f / ang;
        float x = r0 * inv, y = r1 * inv, z = r2 * inv;
        float s, c;
        sincosf(ang, &s, &c);
        float ic = 1.0f - c;
        float R[9];
        R[0] = 1.0f - ic * (y * y + z * z);
        R[1] = -s * z + ic * x * y;
        R[2] =  s * y + ic * x * z;
        R[3] =  s * z + ic * x * y;
        R[4] = 1.0f - ic * (x * x + z * z);
        R[5] = -s * x + ic * y * z;
        R[6] = -s * y + ic * x * z;
        R[7] =  s * x + ic * y * z;
        R[8] = 1.0f - ic * (x * x + y * y);
        #pragma unroll
        for (int m = 0; m < 9; m++) sR[w][lane][m] = R[m];
        if (lane >= 1) {
            int s0 = 11 + (lane - 1) * 9;
            #pragma unroll
            for (int m = 0; m < 9; m++)
                write_hl(xrow, s0 + m, R[m] - ((m == 0 || m == 4 || m == 8) ? 1.0f : 0.0f));
        }
    }
    if (lane == 0)  write_hl(xrow, 0, 1.0f);
    if (lane < 10)  write_hl(xrow, 1 + lane, beta[b * 10 + lane]);

    if (lane < 16) {
        float jx = g_J0[lane * 3 + 0], jy = g_J0[lane * 3 + 1], jz = g_J0[lane * 3 + 2];
        #pragma unroll
        for (int s = 0; s < 10; s++) {
            float bs = beta[b * 10 + s];
            jx = fmaf(bs, g_Js[s * 48 + lane * 3 + 0], jx);
            jy = fmaf(bs, g_Js[s * 48 + lane * 3 + 1], jy);
            jz = fmaf(bs, g_Js[s * 48 + lane * 3 + 2], jz);
        }
        sJ[w][lane][0] = jx; sJ[w][lane][1] = jy; sJ[w][lane][2] = jz;
    }
    __syncwarp();

    if (lane == 0) {
        #pragma unroll
        for (int c = 0; c < 3; c++) {
            #pragma unroll
            for (int d = 0; d < 3; d++) sG[w][0][c * 4 + d] = sR[w][0][c * 3 + d];
            sG[w][0][c * 4 + 3] = sJ[w][0][c];
        }
    }
    __syncwarp();

    if (lane < 5) {
        float pr[9], pt[3];
        #pragma unroll
        for (int c = 0; c < 3; c++) {
            #pragma unroll
            for (int d = 0; d < 3; d++) pr[c * 3 + d] = sG[w][0][c * 4 + d];
            pt[c] = sG[w][0][c * 4 + 3];
        }
        int p = 0;
        #pragma unroll
        for (int st = 0; st < 3; st++) {
            int j = 1 + lane * 3 + st;
            float rj[9];
            #pragma unroll
            for (int m = 0; m < 9; m++) rj[m] = sR[w][j][m];
            float nr[9], nt[3];
            #pragma unroll
            for (int c = 0; c < 3; c++)
                #pragma unroll
                for (int d = 0; d < 3; d++)
                    nr[c * 3 + d] = pr[c * 3 + 0] * rj[0 * 3 + d]
                                  + pr[c * 3 + 1] * rj[1 * 3 + d]
                                  + pr[c * 3 + 2] * rj[2 * 3 + d];
            float dx = sJ[w][j][0] - sJ[w][p][0];
            float dy = sJ[w][j][1] - sJ[w][p][1];
            float dz = sJ[w][j][2] - sJ[w][p][2];
            #pragma unroll
            for (int c = 0; c < 3; c++)
                nt[c] = pr[c * 3 + 0] * dx + pr[c * 3 + 1] * dy + pr[c * 3 + 2] * dz + pt[c];
            #pragma unroll
            for (int c = 0; c < 3; c++) {
                #pragma unroll
                for (int d = 0; d < 3; d++) sG[w][j][c * 4 + d] = nr[c * 3 + d];
                sG[w][j][c * 4 + 3] = nt[c];
            }
            #pragma unroll
            for (int m = 0; m < 9; m++) pr[m] = nr[m];
            pt[0] = nt[0]; pt[1] = nt[1]; pt[2] = nt[2];
            p = j;
        }
    }
    __syncwarp();

    if (lane < 16) {
        float jx = sJ[w][lane][0], jy = sJ[w][lane][1], jz = sJ[w][lane][2];
        #pragma unroll
        for (int c = 0; c < 3; c++) {
            float a0 = sG[w][lane][c * 4 + 0];
            float a1 = sG[w][lane][c * 4 + 1];
            float a2 = sG[w][lane][c * 4 + 2];
            float at = sG[w][lane][c * 4 + 3] - (a0 * jx + a1 * jy + a2 * jz);
            int base = b * 192 + lane * 12 + c * 4;
            g_A[base + 0] = a0; g_A[base + 1] = a1;
            g_A[base + 2] = a2; g_A[base + 3] = at;
        }
    }
}

// =====================================================================
// Kernel 3: fp16 mma.sync GEMM  M[8192,1024] = Xh[8192,512] * Cb[512,1024]
// CTA tile 128x128, BK=32, 3-stage cp.async pipeline, warp tile 64x32.
// =====================================================================
__global__ __launch_bounds__(256) void mma_kernel()
{
    __shared__ __align__(128) __half smA[3][128 * BKC];   // [st][m][k] 64B rows
    __shared__ __align__(128) __half smB[3][BKC * 128];   // [st][k][n] 256B rows

    const int tid = threadIdx.x;
    const int wid = tid >> 5, lane = tid & 31;
    const int bn0 = blockIdx.x * 128;
    const int bm0 = blockIdx.y * 128;
    const int warp_m = (wid & 1) * 64;
    const int warp_n = (wid >> 1) * 32;

    const uint32_t smA_u = (uint32_t)__cvta_generic_to_shared(&smA[0][0]);
    const uint32_t smB_u = (uint32_t)__cvta_generic_to_shared(&smB[0][0]);

    float acc[4][4][4];
    #pragma unroll
    for (int mt = 0; mt < 4; mt++)
        #pragma unroll
        for (int nt = 0; nt < 4; nt++)
            #pragma unroll
            for (int q = 0; q < 4; q++) acc[mt][nt][q] = 0.f;

    auto load_chunk = [&](int kc, int st) {
        // A: 128 rows x 32 halfs (64B) = 512 x 16B chunks; 2 per thread
        #pragma unroll
        for (int i = 0; i < 2; i++) {
            int idx = i * 256 + tid;
            int row = idx >> 2, c16 = idx & 3;
            uint32_t off = SWA((uint32_t)(row * 64 + c16 * 16));
            cp16(smA_u + st * 8192 + off,
                 g_Xh + (size_t)(bm0 + row) * KC + kc * BKC + c16 * 8);
        }
        // B: 32 rows x 128 halfs (256B) = 512 x 16B chunks; 2 per thread
        #pragma unroll
        for (int i = 0; i < 2; i++) {
            int idx = i * 256 + tid;
            int row = idx >> 4, c16 = idx & 15;
            uint32_t off = SWB((uint32_t)(row * 256 + c16 * 16));
            cp16(smB_u + st * 8192 + off,
                 g_Cb + (size_t)(kc * BKC + row) * NP + bn0 + c16 * 8);
        }
    };

    load_chunk(0, 0); CP_COMMIT();
    load_chunk(1, 1); CP_COMMIT();

    const int r15 = lane & 15;
    const int kq  = lane >> 4;

    #pragma unroll 1
    for (int kc = 0; kc < NCH; kc++) {
        CP_WAIT1();
        __syncthreads();
        int nk = kc + 2;
        if (nk < NCH) load_chunk(nk, nk % 3);
        CP_COMMIT();

        int st = kc % 3;
        #pragma unroll
        for (int ks = 0; ks < 2; ks++) {
            uint32_t a[4][4], b[4][2];
            #pragma unroll
            for (int mt = 0; mt < 4; mt++) {
                uint32_t off = (uint32_t)((warp_m + mt * 16 + r15) * 64
                                          + (ks * 16 + kq * 8) * 2);
                ldsm_x4(a[mt], smA_u + st * 8192 + SWA(off));
            }
            #pragma unroll
            for (int nt = 0; nt < 4; nt++) {
                uint32_t off = (uint32_t)((ks * 16 + r15) * 256
                                          + (warp_n + nt * 8) * 2);
                ldsm_x2_t(b[nt], smB_u + st * 8192 + SWB(off));
            }
            #pragma unroll
            for (int mt = 0; mt < 4; mt++)
                #pragma unroll
                for (int nt = 0; nt < 4; nt++)
                    mma16816(acc[mt][nt], a[mt], b[nt]);
        }
    }

    // epilogue: lane l owns rows (l>>2, +8), cols (l&3)*2 within each 16x8 tile
    #pragma unroll
    for (int mt = 0; mt < 4; mt++) {
        #pragma unroll
        for (int nt = 0; nt < 4; nt++) {
            int r0 = bm0 + warp_m + mt * 16 + (lane >> 2);
            int c  = bn0 + warp_n + nt * 8 + (lane & 3) * 2;
            float2 v0 = make_float2(acc[mt][nt][0], acc[mt][nt][1]);
            float2 v1 = make_float2(acc[mt][nt][2], acc[mt][nt][3]);
            *(float2*)&g_M[(size_t)r0 * NP + c] = v0;
            *(float2*)&g_M[(size_t)(r0 + 8) * NP + c] = v1;
        }
    }
}

// =====================================================================
// Kernel 4: joints[b,k,c] = sum_j ( A[b,j,c,:3].M[b,j,k,:] + A[b,j,c,3]*W[k,j] )
// =====================================================================
__global__ __launch_bounds__(256) void reduce_kernel(float* __restrict__ out)
{
    __shared__ float Msh[8][1008];
    __shared__ float Ash[8][192];
    __shared__ float Wsh[336];

    int w = threadIdx.x >> 5, lane = threadIdx.x & 31;
    int b = blockIdx.x * 8 + w;

    for (int i = threadIdx.x; i < 336; i += 256) Wsh[i] = g_W[i];
    #pragma unroll
    for (int r = 0; r < 8; r++) {
        int idx = lane + r * 32;
        if (idx < 252)
            *(float4*)&Msh[w][idx * 4] = *(const float4*)&g_M[(size_t)b * NP + idx * 4];
    }
    #pragma unroll
    for (int r = 0; r < 2; r++) {
        int idx = lane + r * 32;
        if (idx < 48)
            *(float4*)&Ash[w][idx * 4] = *(const float4*)&g_A[b * 192 + idx * 4];
    }
    __syncthreads();

    #pragma unroll
    for (int rep = 0; rep < 2; rep++) {
        int o = lane + rep * 32;
        if (o < 63) {
            int k = o / 3, c = o % 3;
            float acc = 0.f;
            #pragma unroll
            for (int j = 0; j < 16; j++) {
                const float* a = &Ash[w][j * 12 + c * 4];
                const float* m = &Msh[w][(j * 21 + k) * 3];
                acc = fmaf(a[0], m[0], acc);
                acc = fmaf(a[1], m[1], acc);
                acc = fmaf(a[2], m[2], acc);
                acc = fmaf(a[3], Wsh[k * 16 + j], acc);
            }
            out[b * 63 + o] = acc;
        }
    }
}

// =====================================================================
extern "C" void kernel_launch(void* const* d_in, const int* in_sizes, int n_in,
                              void* d_out, int out_size)
{
    const float* beta  = (const float*)d_in[0];
    const float* theta = (const float*)d_in[1];
    const float* wrist = (const float*)d_in[2];
    const float* vt    = (const float*)d_in[3];
    const float* sd    = (const float*)d_in[4];
    const float* pd    = (const float*)d_in[5];
    const float* Jr    = (const float*)d_in[6];
    const float* hc    = (const float*)d_in[7];
    const float* hm    = (const float*)d_in[8];
    const float* wts   = (const float*)d_in[9];
    float* out = (float*)d_out;

    precomp_all<<<173, 1024>>>(vt, sd, pd, Jr, wts);
    fk_kernel<<<1024, 256>>>(beta, theta, wrist, hc, hm);
    mma_kernel<<<dim3(NP / 128, NB / 128), 256>>>();
    reduce_kernel<<<1024, 256>>>(out);
}